// round 15
// baseline (speedup 1.0000x reference)
#include <cuda_runtime.h>
#include <math.h>

#define NMAX 800000
#define DD   128
#define SS   64
#define KK   37          // blocks per segment: 64*37 = 2368 = 148 SMs * 4 CTAs * 4 exact waves
#define EPSF 1e-16f

// ---------------- device scratch (no allocations allowed) ----------------
__device__ int   g_off[SS + 1];
__device__ int   g_cnt[SS];              // zero-init; self-resetting for graph replay
__device__ float g_gate[NMAX];           // stores e = exp(gate) (unshifted)
__device__ float g_pz[SS * KK];          // per-(seg,block) sum exp
__device__ float g_pw[SS * KK * DD];     // per-(seg,block) weighted vec

// ---------------- kernel 1: parallel segment-boundary scan ----------------
// lower_bound semantics: g_off[t] = first i with batch[i] >= t; g_off[SS] = N.
__global__ __launch_bounds__(256) void k_bounds(const void* __restrict__ batch_raw,
                                                int N) {
    const int i = blockIdx.x * blockDim.x + threadIdx.x;
    if (i >= N) return;
    const int* w32 = (const int*)batch_raw;
    // dtype probe (validated in earlier rounds): int64 LE buffers have zero
    // high-words at odd 32-bit indices mid-array; sorted int32 batch has ~32.
    const int h = (N / 2) & ~1;
    const bool is64 = (w32[h + 1] == 0 && w32[h + 3] == 0 && w32[h] > 0);
    const int bi = is64 ? w32[2 * i] : w32[i];
    const int bp = (i == 0) ? -1 : (is64 ? w32[2 * (i - 1)] : w32[i - 1]);
    if (bp != bi) {
        for (int j = bp + 1; j <= bi; j++) g_off[j] = i;
    }
    if (i == N - 1) {
        for (int j = bi + 1; j <= SS; j++) g_off[j] = N;
    }
}

// ---------------- kernel 2: fused gate+pool+combine+gate_sm ----------------
__global__ __launch_bounds__(256, 4) void k_pass1(const float* __restrict__ x,
                                                  const float* __restrict__ gw,
                                                  const float* __restrict__ gb,
                                                  float* __restrict__ out,
                                                  float* __restrict__ gout,
                                                  int write_gate) {
    const int s = blockIdx.x / KK;
    const int k = blockIdx.x - s * KK;

    const int lo = g_off[s], hi = g_off[s + 1];
    const int len = hi - lo;
    const int start = lo + (int)(((long long)len * k) / KK);
    const int end   = lo + (int)(((long long)len * (k + 1)) / KK);

    const int w = threadIdx.x >> 5;
    const int l = threadIdx.x & 31;
    const int t = threadIdx.x;

    const float4 Wv = *(const float4*)(gw + 4 * l);
    const float  bv = *gb;

    float  Z = 0.0f;
    float4 acc = make_float4(0.f, 0.f, 0.f, 0.f);

    int i = start + w;
    // 8-node unroll; no loop-carried max -> deep load pipelining
    for (; i + 56 < end; i += 64) {
        float4 xv[8];
        float  p[8];
        #pragma unroll
        for (int u = 0; u < 8; u++)
            xv[u] = __ldcs((const float4*)(x + (size_t)(i + 8 * u) * DD + 4 * l));
        #pragma unroll
        for (int u = 0; u < 8; u++)
            p[u] = fmaf(xv[u].x, Wv.x, fmaf(xv[u].y, Wv.y, fmaf(xv[u].z, Wv.z, xv[u].w * Wv.w)));
        #pragma unroll
        for (int o = 16; o > 0; o >>= 1) {
            #pragma unroll
            for (int u = 0; u < 8; u++)
                p[u] += __shfl_xor_sync(0xffffffffu, p[u], o);
        }
        float e[8];
        #pragma unroll
        for (int u = 0; u < 8; u++) e[u] = __expf(p[u] + bv);
        if (l == 0) {
            #pragma unroll
            for (int u = 0; u < 8; u++) __stcs(g_gate + i + 8 * u, e[u]);
        }
        #pragma unroll
        for (int u = 0; u < 8; u++) {
            Z += e[u];
            acc.x = fmaf(e[u], xv[u].x, acc.x);
            acc.y = fmaf(e[u], xv[u].y, acc.y);
            acc.z = fmaf(e[u], xv[u].z, acc.z);
            acc.w = fmaf(e[u], xv[u].w, acc.w);
        }
    }
    // tail
    for (; i < end; i += 8) {
        const float4 xv = __ldcs((const float4*)(x + (size_t)i * DD + 4 * l));
        float p = fmaf(xv.x, Wv.x, fmaf(xv.y, Wv.y, fmaf(xv.z, Wv.z, xv.w * Wv.w)));
        #pragma unroll
        for (int o = 16; o > 0; o >>= 1) p += __shfl_xor_sync(0xffffffffu, p, o);
        const float e = __expf(p + bv);
        if (l == 0) __stcs(g_gate + i, e);
        Z += e;
        acc.x = fmaf(e, xv.x, acc.x);
        acc.y = fmaf(e, xv.y, acc.y);
        acc.z = fmaf(e, xv.z, acc.z);
        acc.w = fmaf(e, xv.w, acc.w);
    }

    // -------- block combine (pure sums; no max) --------
    __shared__ float sm_z[8];
    __shared__ float sm_acc[8][DD];
    __shared__ int   s_last;
    __shared__ float s_invZ;
    sm_acc[w][4 * l + 0] = acc.x;
    sm_acc[w][4 * l + 1] = acc.y;
    sm_acc[w][4 * l + 2] = acc.z;
    sm_acc[w][4 * l + 3] = acc.w;
    if (l == 0) sm_z[w] = Z;
    __syncthreads();

    if (t < DD) {
        float a = 0.0f;
        #pragma unroll
        for (int j = 0; j < 8; j++) a += sm_acc[j][t];
        g_pw[(size_t)blockIdx.x * DD + t] = a;
    }
    if (t == 0) {
        float Zb = 0.0f;
        #pragma unroll
        for (int j = 0; j < 8; j++) Zb += sm_z[j];
        g_pz[blockIdx.x] = Zb;
    }

    // -------- last-block-per-segment: final combine + gate_sm --------
    __threadfence();
    __syncthreads();
    if (t == 0) {
        const int old = atomicAdd(&g_cnt[s], 1);
        s_last = (old == KK - 1) ? 1 : 0;
        if (s_last) __threadfence();       // acquire side of the fence/flag pattern
    }
    __syncthreads();
    if (!s_last) return;

    float a = 0.0f;
    if (t < DD) {
        #pragma unroll
        for (int j = 0; j < KK; j++)
            a += __ldcg(&g_pw[(size_t)(s * KK + j) * DD + t]);
    }
    if (t == 0) {
        float Zt = 0.0f;
        #pragma unroll
        for (int j = 0; j < KK; j++) Zt += __ldcg(&g_pz[s * KK + j]);
        s_invZ   = 1.0f / (Zt + EPSF);
        g_cnt[s] = 0;                      // reset for next graph replay
    }
    __syncthreads();
    const float invZ = s_invZ;
    if (t < DD) out[s * DD + t] = a * invZ;

    if (!write_gate) return;

    // gate_sm for the whole segment [lo, hi): e * invZ. g_gate is L2-resident.
    const int a0 = min((lo + 3) & ~3, hi);   // align head
    const int a1 = max(hi & ~3, a0);         // aligned end
    for (int j = lo + t; j < a0; j += 256)
        gout[j] = __ldcg(g_gate + j) * invZ;
    for (int j4 = (a0 >> 2) + t; 4 * j4 < a1; j4 += 256) {
        const float4 e = __ldcg((const float4*)g_gate + j4);
        float4 r;
        r.x = e.x * invZ; r.y = e.y * invZ; r.z = e.z * invZ; r.w = e.w * invZ;
        *((float4*)gout + j4) = r;
    }
    for (int j = a1 + t; j < hi; j += 256)
        gout[j] = __ldcg(g_gate + j) * invZ;
}

// ---------------- launcher ----------------
extern "C" void kernel_launch(void* const* d_in, const int* in_sizes, int n_in,
                              void* d_out, int out_size) {
    const float* x     = (const float*)d_in[0];
    const void*  batch = d_in[1];
    const float* gw    = (const float*)d_in[n_in - 2];  // [D,1]
    const float* gb    = (const float*)d_in[n_in - 1];  // [1]
    const int N = in_sizes[1];

    float* out  = (float*)d_out;             // [S, D] first
    float* gout = out + SS * DD;             // then gate_sm [N]
    const int write_gate = (out_size >= SS * DD + N) ? 1 : 0;

    k_bounds<<<(N + 255) / 256, 256>>>(batch, N);
    k_pass1<<<SS * KK, 256>>>(x, gw, gb, out, gout, write_gate);
}